// round 1
// baseline (speedup 1.0000x reference)
#include <cuda_runtime.h>

#define MB 32
#define NP 256
#define ND 512

// scratch (no allocations allowed)
__device__ float g_cd[MB * MB];
__device__ float g_rowsum[MB];

// ---------------------------------------------------------------------------
// Kernel A: all-pairs Chamfer distance over shapes = xyz[32:], symmetric.
// grid (32,32), block 256. Blocks with i>j exit (cd symmetric).
// ---------------------------------------------------------------------------
__global__ void chamfer_kernel(const float* __restrict__ xyz) {
    const int i = blockIdx.x, j = blockIdx.y;
    if (i > j) return;

    __shared__ float4 s_i[NP];
    __shared__ float4 s_j[NP];
    __shared__ float  s_red[8];

    const int t = threadIdx.x;
    const float* shapes = xyz + MB * NP * 3;

    {
        const float* pi = shapes + (i * NP + t) * 3;
        float x = pi[0], y = pi[1], z = pi[2];
        s_i[t] = make_float4(x, y, z, x * x + y * y + z * z);
        const float* pj = shapes + (j * NP + t) * 3;
        float xb = pj[0], yb = pj[1], zb = pj[2];
        s_j[t] = make_float4(xb, yb, zb, xb * xb + yb * yb + zb * zb);
    }
    __syncthreads();

    const float4 a = s_i[t];  // my point in shape i (role A: min over q in j)
    const float4 b = s_j[t];  // my point in shape j (role B: min over p in i)

    const float INF = 3.4e38f;
    float mA0 = INF, mA1 = INF, mA2 = INF, mA3 = INF;
    float mB0 = INF, mB1 = INF, mB2 = INF, mB3 = INF;

#pragma unroll 4
    for (int q = 0; q < NP; q += 4) {
#pragma unroll
        for (int u = 0; u < 4; u++) {
            float4 bq = s_j[q + u];
            float dot = a.x * bq.x + a.y * bq.y + a.z * bq.z;
            float d2 = a.w + bq.w - 2.f * dot;
            float4 ap = s_i[q + u];
            float dot2 = ap.x * b.x + ap.y * b.y + ap.z * b.z;
            float e2 = ap.w + b.w - 2.f * dot2;
            if (u == 0) { mA0 = fminf(mA0, d2); mB0 = fminf(mB0, e2); }
            if (u == 1) { mA1 = fminf(mA1, d2); mB1 = fminf(mB1, e2); }
            if (u == 2) { mA2 = fminf(mA2, d2); mB2 = fminf(mB2, e2); }
            if (u == 3) { mA3 = fminf(mA3, d2); mB3 = fminf(mB3, e2); }
        }
    }
    float minA = fminf(fminf(mA0, mA1), fminf(mA2, mA3));
    float minB = fminf(fminf(mB0, mB1), fminf(mB2, mB3));

    // block-reduce sum of (minA + minB)
    float s = minA + minB;
#pragma unroll
    for (int o = 16; o > 0; o >>= 1) s += __shfl_down_sync(0xffffffffu, s, o);
    if ((t & 31) == 0) s_red[t >> 5] = s;
    __syncthreads();
    if (t == 0) {
        float tot = 0.f;
#pragma unroll
        for (int w = 0; w < 8; w++) tot += s_red[w];
        float cd = tot * (1.f / NP);
        g_cd[i * MB + j] = cd;
        g_cd[j * MB + i] = cd;
    }
}

// ---------------------------------------------------------------------------
// Kernel B: per-row finalize. Block i computes:
//   inner_dot row i (normalized), softmax -> p_hat row
//   p row from cd, softmax(-cd^2/(2 sigma^2))
//   g_rowsum[i] = sum_j |p_hat - p|
// grid 32, block 256.
// ---------------------------------------------------------------------------
__global__ void finalize_kernel(const float* __restrict__ emb) {
    const int i = blockIdx.x;
    __shared__ float s_ei[ND];
    __shared__ float s_dot[MB];
    __shared__ float s_red[8];
    __shared__ float s_invni;

    const int t = threadIdx.x;
    float v0 = emb[i * ND + t];
    float v1 = emb[i * ND + 256 + t];
    s_ei[t] = v0;
    s_ei[t + 256] = v1;

    // norm of sketch row i
    float ss = v0 * v0 + v1 * v1;
#pragma unroll
    for (int o = 16; o > 0; o >>= 1) ss += __shfl_down_sync(0xffffffffu, ss, o);
    if ((t & 31) == 0) s_red[t >> 5] = ss;
    __syncthreads();
    if (t == 0) {
        float tot = 0.f;
#pragma unroll
        for (int w = 0; w < 8; w++) tot += s_red[w];
        s_invni = rsqrtf(tot);
    }
    __syncthreads();

    const int w = t >> 5, lane = t & 31;
    // each warp computes 4 of the 32 dot products (row i of inner_dot)
    for (int j = w; j < MB; j += 8) {
        const float* ej = emb + (MB + j) * ND;
        float dot = 0.f, nj = 0.f;
#pragma unroll 4
        for (int k = lane; k < ND; k += 32) {
            float e = ej[k];
            dot += e * s_ei[k];
            nj += e * e;
        }
#pragma unroll
        for (int o = 16; o > 0; o >>= 1) {
            dot += __shfl_down_sync(0xffffffffu, dot, o);
            nj  += __shfl_down_sync(0xffffffffu, nj, o);
        }
        if (lane == 0) s_dot[j] = dot * rsqrtf(nj) * s_invni;
    }
    __syncthreads();

    if (w == 0) {
        // lane handles column `lane` of row i
        float idot = s_dot[lane];
        float m = idot;
#pragma unroll
        for (int o = 16; o > 0; o >>= 1) m = fmaxf(m, __shfl_xor_sync(0xffffffffu, m, o));
        float e = expf(idot - m);
        float sum = e;
#pragma unroll
        for (int o = 16; o > 0; o >>= 1) sum += __shfl_xor_sync(0xffffffffu, sum, o);
        float p_hat = e / sum;

        const float SIG = 1.0f * 0.997f / 3.0f;
        const float INV2S2 = 1.0f / (2.0f * SIG * SIG);
        float cd = g_cd[i * MB + lane];
        float nd = -(cd * cd) * INV2S2;
        float m2 = nd;
#pragma unroll
        for (int o = 16; o > 0; o >>= 1) m2 = fmaxf(m2, __shfl_xor_sync(0xffffffffu, m2, o));
        float e2 = expf(nd - m2);
        float sum2 = e2;
#pragma unroll
        for (int o = 16; o > 0; o >>= 1) sum2 += __shfl_xor_sync(0xffffffffu, sum2, o);
        float p = e2 / sum2;

        float diff = fabsf(p_hat - p);
#pragma unroll
        for (int o = 16; o > 0; o >>= 1) diff += __shfl_xor_sync(0xffffffffu, diff, o);
        if (lane == 0) g_rowsum[i] = diff;
    }
}

// ---------------------------------------------------------------------------
// Kernel C: deterministic final reduction -> scalar output.
// ---------------------------------------------------------------------------
__global__ void reduce_kernel(float* __restrict__ out) {
    float v = g_rowsum[threadIdx.x];
#pragma unroll
    for (int o = 16; o > 0; o >>= 1) v += __shfl_down_sync(0xffffffffu, v, o);
    if (threadIdx.x == 0) out[0] = v * (1.0f / (MB * MB));
}

extern "C" void kernel_launch(void* const* d_in, const int* in_sizes, int n_in,
                              void* d_out, int out_size) {
    const float* embeddings = (const float*)d_in[0];  // (64, 512) fp32
    const float* xyz        = (const float*)d_in[1];  // (64, 256, 3) fp32
    float* out = (float*)d_out;

    dim3 grid_cd(MB, MB);
    chamfer_kernel<<<grid_cd, NP>>>(xyz);
    finalize_kernel<<<MB, 256>>>(embeddings);
    reduce_kernel<<<1, 32>>>(out);
}

// round 3
// speedup vs baseline: 1.3406x; 1.3406x over previous
#include <cuda_runtime.h>

#define MB 32
#define NP 256
#define ND 512

// scratch (no allocations allowed)
__device__ float g_D[MB * MB];      // D(i,j) = mean_p min_q d2
__device__ float g_rowsum[MB];

// ---------------------------------------------------------------------------
// Kernel A: one-directional chamfer D(i,j) for ALL ordered pairs.
// grid (32,32), block 256 (one thread per point p of shape i).
// d2 factored: min_q(|a|^2+|b|^2-2ab) = |a|^2 + min_q(|b|^2 - 2 a.b)
// inner body: 1 LDS.128 + 3 FFMA + 1 FMNMX.
// ---------------------------------------------------------------------------
__global__ void chamfer_dir_kernel(const float* __restrict__ xyz) {
    const int i = blockIdx.x, j = blockIdx.y;

    __shared__ float4 s_j[NP];
    __shared__ float  s_red[8];

    const int t = threadIdx.x;
    const float* shapes = xyz + MB * NP * 3;

    // stage shape j (opponent) into smem with precomputed |b|^2
    {
        const float* pj = shapes + (j * NP + t) * 3;
        float xb = pj[0], yb = pj[1], zb = pj[2];
        s_j[t] = make_float4(xb, yb, zb, xb * xb + yb * yb + zb * zb);
    }

    // my point p = t of shape i, pre-scaled by -2
    const float* pi = shapes + (i * NP + t) * 3;
    float ax = pi[0], ay = pi[1], az = pi[2];
    const float aw  = ax * ax + ay * ay + az * az;
    const float a2x = -2.0f * ax, a2y = -2.0f * ay, a2z = -2.0f * az;

    __syncthreads();

    const float INF = 3.4e38f;
    float m0 = INF, m1 = INF, m2 = INF, m3 = INF;

#pragma unroll 2
    for (int q = 0; q < NP; q += 8) {
        float4 b0 = s_j[q + 0];
        float4 b1 = s_j[q + 1];
        float4 b2 = s_j[q + 2];
        float4 b3 = s_j[q + 3];
        float4 b4 = s_j[q + 4];
        float4 b5 = s_j[q + 5];
        float4 b6 = s_j[q + 6];
        float4 b7 = s_j[q + 7];
        float s0 = fmaf(a2x, b0.x, fmaf(a2y, b0.y, fmaf(a2z, b0.z, b0.w)));
        float s1 = fmaf(a2x, b1.x, fmaf(a2y, b1.y, fmaf(a2z, b1.z, b1.w)));
        float s2 = fmaf(a2x, b2.x, fmaf(a2y, b2.y, fmaf(a2z, b2.z, b2.w)));
        float s3 = fmaf(a2x, b3.x, fmaf(a2y, b3.y, fmaf(a2z, b3.z, b3.w)));
        float s4 = fmaf(a2x, b4.x, fmaf(a2y, b4.y, fmaf(a2z, b4.z, b4.w)));
        float s5 = fmaf(a2x, b5.x, fmaf(a2y, b5.y, fmaf(a2z, b5.z, b5.w)));
        float s6 = fmaf(a2x, b6.x, fmaf(a2y, b6.y, fmaf(a2z, b6.z, b6.w)));
        float s7 = fmaf(a2x, b7.x, fmaf(a2y, b7.y, fmaf(a2z, b7.z, b7.w)));
        m0 = fminf(m0, s0);
        m1 = fminf(m1, s1);
        m2 = fminf(m2, s2);
        m3 = fminf(m3, s3);
        m0 = fminf(m0, s4);
        m1 = fminf(m1, s5);
        m2 = fminf(m2, s6);
        m3 = fminf(m3, s7);
    }
    float minv = fminf(fminf(m0, m1), fminf(m2, m3)) + aw;

    // block-reduce sum of mins
    float s = minv;
#pragma unroll
    for (int o = 16; o > 0; o >>= 1) s += __shfl_down_sync(0xffffffffu, s, o);
    if ((t & 31) == 0) s_red[t >> 5] = s;
    __syncthreads();
    if (t == 0) {
        float tot = 0.f;
#pragma unroll
        for (int w = 0; w < 8; w++) tot += s_red[w];
        g_D[i * MB + j] = tot * (1.f / NP);
    }
}

// ---------------------------------------------------------------------------
// Kernel B: per-row finalize. Block i computes:
//   inner_dot row i (normalized), softmax -> p_hat row
//   p row from cd = D(i,j)+D(j,i), softmax(-cd^2/(2 sigma^2))
//   g_rowsum[i] = sum_j |p_hat - p|
// grid 32, block 256.
// ---------------------------------------------------------------------------
__global__ void finalize_kernel(const float* __restrict__ emb) {
    const int i = blockIdx.x;
    __shared__ float s_ei[ND];
    __shared__ float s_dot[MB];
    __shared__ float s_red[8];
    __shared__ float s_invni;

    const int t = threadIdx.x;
    float v0 = emb[i * ND + t];
    float v1 = emb[i * ND + 256 + t];
    s_ei[t] = v0;
    s_ei[t + 256] = v1;

    // norm of sketch row i
    float ss = v0 * v0 + v1 * v1;
#pragma unroll
    for (int o = 16; o > 0; o >>= 1) ss += __shfl_down_sync(0xffffffffu, ss, o);
    if ((t & 31) == 0) s_red[t >> 5] = ss;
    __syncthreads();
    if (t == 0) {
        float tot = 0.f;
#pragma unroll
        for (int w = 0; w < 8; w++) tot += s_red[w];
        s_invni = rsqrtf(tot);
    }
    __syncthreads();

    const int w = t >> 5, lane = t & 31;
    // each warp computes 4 of the 32 dot products (row i of inner_dot)
    for (int j = w; j < MB; j += 8) {
        const float* ej = emb + (MB + j) * ND;
        float dot = 0.f, nj = 0.f;
#pragma unroll 4
        for (int k = lane; k < ND; k += 32) {
            float e = ej[k];
            dot += e * s_ei[k];
            nj += e * e;
        }
#pragma unroll
        for (int o = 16; o > 0; o >>= 1) {
            dot += __shfl_down_sync(0xffffffffu, dot, o);
            nj  += __shfl_down_sync(0xffffffffu, nj, o);
        }
        if (lane == 0) s_dot[j] = dot * rsqrtf(nj) * s_invni;
    }
    __syncthreads();

    if (w == 0) {
        // lane handles column `lane` of row i
        float idot = s_dot[lane];
        float m = idot;
#pragma unroll
        for (int o = 16; o > 0; o >>= 1) m = fmaxf(m, __shfl_xor_sync(0xffffffffu, m, o));
        float e = expf(idot - m);
        float sum = e;
#pragma unroll
        for (int o = 16; o > 0; o >>= 1) sum += __shfl_xor_sync(0xffffffffu, sum, o);
        float p_hat = e / sum;

        const float SIG = 1.0f * 0.997f / 3.0f;
        const float INV2S2 = 1.0f / (2.0f * SIG * SIG);
        float cd = g_D[i * MB + lane] + g_D[lane * MB + i];
        float nd = -(cd * cd) * INV2S2;
        float m2 = nd;
#pragma unroll
        for (int o = 16; o > 0; o >>= 1) m2 = fmaxf(m2, __shfl_xor_sync(0xffffffffu, m2, o));
        float e2 = expf(nd - m2);
        float sum2 = e2;
#pragma unroll
        for (int o = 16; o > 0; o >>= 1) sum2 += __shfl_xor_sync(0xffffffffu, sum2, o);
        float p = e2 / sum2;

        float diff = fabsf(p_hat - p);
#pragma unroll
        for (int o = 16; o > 0; o >>= 1) diff += __shfl_xor_sync(0xffffffffu, diff, o);
        if (lane == 0) g_rowsum[i] = diff;
    }
}

// ---------------------------------------------------------------------------
// Kernel C: deterministic final reduction -> scalar output.
// ---------------------------------------------------------------------------
__global__ void reduce_kernel(float* __restrict__ out) {
    float v = g_rowsum[threadIdx.x];
#pragma unroll
    for (int o = 16; o > 0; o >>= 1) v += __shfl_down_sync(0xffffffffu, v, o);
    if (threadIdx.x == 0) out[0] = v * (1.0f / (MB * MB));
}

extern "C" void kernel_launch(void* const* d_in, const int* in_sizes, int n_in,
                              void* d_out, int out_size) {
    const float* embeddings = (const float*)d_in[0];  // (64, 512) fp32
    const float* xyz        = (const float*)d_in[1];  // (64, 256, 3) fp32
    float* out = (float*)d_out;

    dim3 grid_cd(MB, MB);
    chamfer_dir_kernel<<<grid_cd, NP>>>(xyz);
    finalize_kernel<<<MB, 256>>>(embeddings);
    reduce_kernel<<<1, 32>>>(out);
}